// round 1
// baseline (speedup 1.0000x reference)
#include <cuda_runtime.h>

// ---------------- geometry ----------------
#define RAD    7
#define IMG    2048
#define DOM    2062            // IMG + 2*RAD : iterated domain
#define GUARD  8               // zero guard band around DOM (zero-pad semantics)
#define WB     2176            // buffer width in floats (>= 9*240 + 256)
#define W4     (WB/4)
#define HB     2080            // buffer height (>= GUARD + DOM + GUARD, + slide slack)
#define PLANE  (HB*WB)
#define COLB   240             // output columns per block
#define NCB    9               // ceil(DOM/COLB)
#define SROWS  40              // output rows per block
#define NRB    52              // ceil(DOM/SROWS)
#define NITER  10

// ping-pong state, planar per channel, guard bands stay zero forever
__device__ float g_bufA[3*PLANE];
__device__ float g_bufB[3*PLANE];

// ---------------- pad: img (HWC, edge-pad 7) -> bufA planar; bufB = 0 ----------------
__global__ void pad_kernel(const float* __restrict__ img) {
    int idx = blockIdx.x*blockDim.x + threadIdx.x;
    if (idx >= PLANE) return;
    int ch = blockIdx.y;
    int br = idx / WB, bc = idx % WB;
    float v = 0.f;
    if (br >= GUARD && br < GUARD+DOM && bc >= GUARD && bc < GUARD+DOM) {
        int u = br - (GUARD+RAD);          // image row of edge-padded U
        int w = bc - (GUARD+RAD);
        u = min(max(u,0), IMG-1);
        w = min(max(w,0), IMG-1);
        v = img[(u*IMG + w)*3 + ch];
    }
    g_bufA[ch*PLANE + idx] = v;
    g_bufB[ch*PLANE + idx] = 0.f;
}

// ---------------- helpers ----------------
__device__ __forceinline__ float4 f4add(float4 a, float4 b){
    return make_float4(a.x+b.x, a.y+b.y, a.z+b.z, a.w+b.w);
}
__device__ __forceinline__ float4 f4sub(float4 a, float4 b){
    return make_float4(a.x-b.x, a.y-b.y, a.z-b.z, a.w-b.w);
}

// horizontal 8-wide left/right window sums for 4 consecutive outputs,
// from 20 consecutive values (w[k] = value at col cb-8+k).
// left_j  = sum w[j+1 .. j+8], right_j = sum w[j+8 .. j+15]
__device__ __forceinline__ void hwin(const float* w, float* l, float* r) {
    float s = w[1]+w[2]+w[3]+w[4]+w[5]+w[6]+w[7]+w[8];
    l[0] = s;
    s += w[9]  - w[1]; l[1] = s;
    s += w[10] - w[2]; l[2] = s;
    s += w[11] - w[3]; l[3] = s;
    float q = w[8]+w[9]+w[10]+w[11]+w[12]+w[13]+w[14]+w[15];
    r[0] = q;
    q += w[16] - w[8];  r[1] = q;
    q += w[17] - w[9];  r[2] = q;
    q += w[18] - w[10]; r[3] = q;
}

__device__ __forceinline__ void unpack5(const float4* base, int t, float* w) {
    float4 q0 = base[t-2], q1 = base[t-1], q2 = base[t], q3 = base[t+1], q4 = base[t+2];
    w[0]=q0.x;  w[1]=q0.y;  w[2]=q0.z;  w[3]=q0.w;
    w[4]=q1.x;  w[5]=q1.y;  w[6]=q1.z;  w[7]=q1.w;
    w[8]=q2.x;  w[9]=q2.y;  w[10]=q2.z; w[11]=q2.w;
    w[12]=q3.x; w[13]=q3.y; w[14]=q3.z; w[15]=q3.w;
    w[16]=q4.x; w[17]=q4.y; w[18]=q4.z; w[19]=q4.w;
}

// ---------------- one full side-window iteration, fused ----------------
__global__ __launch_bounds__(64) void iter_kernel(int sel) {
    __shared__ float4 smA[2][64];   // vertical top-8 sums
    __shared__ float4 smB[2][64];   // vertical bottom-8 sums
    __shared__ float4 smX[2][64];   // center row x
    const int t  = threadIdx.x;
    const int ch = blockIdx.z;
    const float* __restrict__ srcp = (sel ? g_bufB : g_bufA) + ch*PLANE;
    float*       __restrict__ dstp = (sel ? g_bufA : g_bufB) + ch*PLANE;
    const float4* __restrict__ src4 = reinterpret_cast<const float4*>(srcp);

    const int c4 = blockIdx.x*(COLB/4) + t;   // float4 column index in buffer
    const int cb = 4*c4;                      // buffer column
    const int r0 = blockIdx.y*SROWS;          // first output row (domain coords)
    const int rend = min(r0 + SROWS, DOM);

    // warm-up vertical sums for row r0:
    // sT = x[r0-7 .. r0]  -> buffer rows r0+1 .. r0+8
    // sB = x[r0   .. r0+7]-> buffer rows r0+8 .. r0+15
    float4 sT = make_float4(0,0,0,0), sB = make_float4(0,0,0,0);
    #pragma unroll
    for (int k = 1; k <= 8; ++k)  sT = f4add(sT, __ldg(&src4[(r0+k)*W4 + c4]));
    #pragma unroll
    for (int k = 8; k <= 15; ++k) sB = f4add(sB, __ldg(&src4[(r0+k)*W4 + c4]));

    const bool isOut = (t >= 2) && (t < 62) && (cb < GUARD+DOM);
    const bool full4 = (cb + 3 < GUARD+DOM);
    const float S8  = 1.0f/64.0f;
    const float S15 = 1.0f/120.0f;

    for (int i = r0; i < rend; ++i) {
        float4 xc = __ldg(&src4[(i+8)*W4 + c4]);   // x at center row i
        const int s = i & 1;
        smA[s][t] = sT; smB[s][t] = sB; smX[s][t] = xc;
        __syncthreads();

        if (isOut) {
            float w[20];
            float lA[4], rA[4], lB[4], rB[4], lX[4], rX[4];
            float cA[4], cB[4];
            unpack5(&smA[s][0], t, w);
            hwin(w, lA, rA);
            cA[0]=w[8]; cA[1]=w[9]; cA[2]=w[10]; cA[3]=w[11];
            unpack5(&smB[s][0], t, w);
            hwin(w, lB, rB);
            cB[0]=w[8]; cB[1]=w[9]; cB[2]=w[10]; cB[3]=w[11];
            unpack5(&smX[s][0], t, w);
            hwin(w, lX, rX);

            float xcv[4] = { xc.x, xc.y, xc.z, xc.w };
            float res[4];
            #pragma unroll
            for (int j = 0; j < 4; ++j) {
                float fAj = lA[j] + rA[j] - cA[j];       // full-15 horiz of top sums
                float fBj = lB[j] + rB[j] - cB[j];       // full-15 horiz of bottom sums
                float lCj = lA[j] + lB[j] - lX[j];       // left-8 of full-15 vertical
                float rCj = rA[j] + rB[j] - rX[j];       // right-8 of full-15 vertical
                float xv = xcv[j];
                // channel order must match reference kernel stack order:
                float d0 = fmaf(lA[j], S8,  -xv);  // NW
                float d1 = fmaf(rA[j], S8,  -xv);  // NE
                float d2 = fmaf(lB[j], S8,  -xv);  // SW
                float d3 = fmaf(rB[j], S8,  -xv);  // SE
                float d4 = fmaf(fAj,   S15, -xv);  // N
                float d5 = fmaf(fBj,   S15, -xv);  // S
                float d6 = fmaf(lCj,   S15, -xv);  // W
                float d7 = fmaf(rCj,   S15, -xv);  // E
                float best = d0, ab = fabsf(d0);
                float a;
                a = fabsf(d1); if (a < ab) { ab = a; best = d1; }
                a = fabsf(d2); if (a < ab) { ab = a; best = d2; }
                a = fabsf(d3); if (a < ab) { ab = a; best = d3; }
                a = fabsf(d4); if (a < ab) { ab = a; best = d4; }
                a = fabsf(d5); if (a < ab) { ab = a; best = d5; }
                a = fabsf(d6); if (a < ab) { ab = a; best = d6; }
                a = fabsf(d7); if (a < ab) { ab = a; best = d7; }
                res[j] = xv + best;
            }
            if (full4) {
                reinterpret_cast<float4*>(dstp)[(i+8)*W4 + c4] =
                    make_float4(res[0], res[1], res[2], res[3]);
            } else {
                #pragma unroll
                for (int k = 0; k < 4; ++k)
                    if (cb + k < GUARD+DOM) dstp[(i+8)*WB + cb + k] = res[k];
            }
        }

        // slide vertical windows to row i+1 (guard rows provide zeros; rows < HB)
        float4 aT = __ldg(&src4[(i+9)*W4  + c4]);
        float4 bT = __ldg(&src4[(i+1)*W4  + c4]);
        float4 aB = __ldg(&src4[(i+16)*W4 + c4]);
        sT = f4sub(f4add(sT, aT), bT);
        sB = f4sub(f4add(sB, aB), xc);
    }
}

// ---------------- crop: bufA planar -> d_out HWC ----------------
__global__ void crop_kernel(float* __restrict__ out) {
    int x = blockIdx.x*blockDim.x + threadIdx.x;
    int y = blockIdx.y;
    if (x >= IMG) return;
    int br = y + RAD + GUARD;
    int bc = x + RAD + GUARD;
    float* o = out + (size_t)(y*IMG + x)*3;
    o[0] = g_bufA[0*PLANE + br*WB + bc];
    o[1] = g_bufA[1*PLANE + br*WB + bc];
    o[2] = g_bufA[2*PLANE + br*WB + bc];
}

extern "C" void kernel_launch(void* const* d_in, const int* in_sizes, int n_in,
                              void* d_out, int out_size) {
    (void)in_sizes; (void)n_in; (void)out_size;
    const float* img = (const float*)d_in[0];   // kernels d_in[1], d_in[2] are fixed constants
    float* out = (float*)d_out;

    dim3 pg((PLANE + 255)/256, 3);
    pad_kernel<<<pg, 256>>>(img);

    for (int it = 0; it < NITER; ++it)
        iter_kernel<<<dim3(NCB, NRB, 3), 64>>>(it & 1);
    // it=0: A->B, it=1: B->A, ... it=9: B->A  => final state in g_bufA

    crop_kernel<<<dim3((IMG + 255)/256, IMG), 256>>>(out);
}

// round 2
// speedup vs baseline: 1.2792x; 1.2792x over previous
#include <cuda_runtime.h>

// ---------------- geometry ----------------
#define RAD    7
#define IMG    2048
#define DOM    2062            // IMG + 2*RAD : iterated domain
#define GUARD  8               // zero guard band around DOM (zero-pad semantics)
#define WB     2176            // buffer width in floats
#define W4     (WB/4)
#define HB     2080            // buffer height
#define PLANE  (HB*WB)
#define NSTRIP 19              // 19 strips * 28 float4 = 532 >= 516 domain float4 cols
#define SROWS  24
#define NRB    86              // ceil(2062/24)
#define NITER  10

// ping-pong state, planar per channel, guard bands stay zero forever
__device__ float g_bufA[3*PLANE];
__device__ float g_bufB[3*PLANE];

// ---------------- pad: img (HWC, edge-pad 7) -> bufA planar; bufB = 0 ----------------
__global__ void pad_kernel(const float* __restrict__ img) {
    int idx = blockIdx.x*blockDim.x + threadIdx.x;
    if (idx >= PLANE) return;
    int ch = blockIdx.y;
    int br = idx / WB, bc = idx % WB;
    float v = 0.f;
    if (br >= GUARD && br < GUARD+DOM && bc >= GUARD && bc < GUARD+DOM) {
        int u = br - (GUARD+RAD);
        int w = bc - (GUARD+RAD);
        u = min(max(u,0), IMG-1);
        w = min(max(w,0), IMG-1);
        v = img[(u*IMG + w)*3 + ch];
    }
    g_bufA[ch*PLANE + idx] = v;
    g_bufB[ch*PLANE + idx] = 0.f;
}

__device__ __forceinline__ float4 f4add(float4 a, float4 b){
    return make_float4(a.x+b.x, a.y+b.y, a.z+b.z, a.w+b.w);
}
__device__ __forceinline__ float4 f4sub(float4 a, float4 b){
    return make_float4(a.x-b.x, a.y-b.y, a.z-b.z, a.w-b.w);
}

// incremental left/right 8-windows from (fine[t-2], ownfine, fine[t+2], chunk sums)
// l[j] = sum w[j+1..j+8], r[j] = sum w[j+8..j+15] with w[k] = value at col 4*(t-2)+k
__device__ __forceinline__ void hwin_cs(float4 fm, float4 own, float4 fp,
                                        float Cm2, float Cm1, float Cown, float Cp1,
                                        float* l, float* r) {
    l[0] = (Cm2 - fm.x) + Cm1 + own.x;
    l[1] = l[0] - fm.y + own.y;
    l[2] = l[1] - fm.z + own.z;
    l[3] = l[2] - fm.w + own.w;
    r[0] = Cown + Cp1;
    r[1] = r[0] - own.x + fp.x;
    r[2] = r[1] - own.y + fp.y;
    r[3] = r[2] - own.z + fp.z;
}

// ---------------- one full side-window iteration, warp-autonomous ----------------
__global__ __launch_bounds__(128,7) void iter_kernel(int sel) {
    __shared__ float4 sF[3][4][32];   // [array: T,B,X][warp][lane] fine float4
    __shared__ float  sC[3][4][32];   // chunk sums

    const int t = threadIdx.x & 31;
    const int w = threadIdx.x >> 5;
    const int strip = blockIdx.x*4 + w;
    if (strip >= NSTRIP) return;      // safe: no __syncthreads in this kernel
    const int ch = blockIdx.z;
    const float* __restrict__ srcp = (sel ? g_bufB : g_bufA) + ch*PLANE;
    float*       __restrict__ dstp = (sel ? g_bufA : g_bufB) + ch*PLANE;
    const float4* __restrict__ src4 = reinterpret_cast<const float4*>(srcp);
    float4*       __restrict__ dst4 = reinterpret_cast<float4*>(dstp);

    const int c4 = strip*28 + t;      // buffer float4 column (max 535 < 544)
    const int r0 = blockIdx.y*SROWS;
    const int rend = min(r0 + SROWS, DOM);

    // warm-up: sT = buffer rows r0+1..r0+8, sB = rows r0+8..r0+15, xc = row r0+8
    float4 sT = make_float4(0,0,0,0), sB = make_float4(0,0,0,0), xc = make_float4(0,0,0,0);
    #pragma unroll
    for (int k = 1; k <= 15; ++k) {
        float4 v = __ldg(&src4[(r0+k)*W4 + c4]);
        if (k <= 8) sT = f4add(sT, v);
        if (k >= 8) sB = f4add(sB, v);
        if (k == 8) xc = v;
    }

    const bool isOut = (t >= 2) && (t < 30) && (c4 <= 517);
    const bool full4 = (c4 <= 516);
    const float S8  = 1.0f/64.0f;
    const float S15 = 1.0f/120.0f;

    for (int i = r0; i < rend; ++i) {
        // prefetch this row's slide inputs early (consumed only at loop bottom)
        float4 aT = __ldg(&src4[(i+9)*W4  + c4]);   // also next row's center
        float4 bT = __ldg(&src4[(i+1)*W4  + c4]);
        float4 aB = __ldg(&src4[(i+16)*W4 + c4]);

        float cT = (sT.x+sT.y)+(sT.z+sT.w);
        float cB = (sB.x+sB.y)+(sB.z+sB.w);
        float cX = (xc.x+xc.y)+(xc.z+xc.w);

        __syncwarp();
        sF[0][w][t] = sT; sC[0][w][t] = cT;
        sF[1][w][t] = sB; sC[1][w][t] = cB;
        sF[2][w][t] = xc; sC[2][w][t] = cX;
        __syncwarp();

        if (isOut) {
            float lA[4], rA[4], lB[4], rB[4], lX[4], rX[4];
            {
                float4 fm = sF[0][w][t-2], fp = sF[0][w][t+2];
                hwin_cs(fm, sT, fp, sC[0][w][t-2], sC[0][w][t-1], cT, sC[0][w][t+1], lA, rA);
            }
            {
                float4 fm = sF[1][w][t-2], fp = sF[1][w][t+2];
                hwin_cs(fm, sB, fp, sC[1][w][t-2], sC[1][w][t-1], cB, sC[1][w][t+1], lB, rB);
            }
            {
                float4 fm = sF[2][w][t-2], fp = sF[2][w][t+2];
                hwin_cs(fm, xc, fp, sC[2][w][t-2], sC[2][w][t-1], cX, sC[2][w][t+1], lX, rX);
            }

            const float cAj[4] = { sT.x, sT.y, sT.z, sT.w };
            const float cBj[4] = { sB.x, sB.y, sB.z, sB.w };
            const float xv [4] = { xc.x, xc.y, xc.z, xc.w };
            float res[4];
            #pragma unroll
            for (int j = 0; j < 4; ++j) {
                float fA = lA[j] + rA[j] - cAj[j];      // full-15 horiz of top sums
                float fB = lB[j] + rB[j] - cBj[j];      // full-15 horiz of bottom sums
                float lC = lA[j] + lB[j] - lX[j];       // left-8 of full-15 vertical
                float rC = rA[j] + rB[j] - rX[j];       // right-8 of full-15 vertical
                float x  = xv[j];
                // channel order matches reference stack: NW NE SW SE N S W E
                float d0 = fmaf(lA[j], S8,  -x);
                float d1 = fmaf(rA[j], S8,  -x);
                float d2 = fmaf(lB[j], S8,  -x);
                float d3 = fmaf(rB[j], S8,  -x);
                float d4 = fmaf(fA,    S15, -x);
                float d5 = fmaf(fB,    S15, -x);
                float d6 = fmaf(lC,    S15, -x);
                float d7 = fmaf(rC,    S15, -x);
                float a0 = fabsf(d0), a1 = fabsf(d1), a2 = fabsf(d2), a3 = fabsf(d3);
                float a4 = fabsf(d4), a5 = fabsf(d5), a6 = fabsf(d6), a7 = fabsf(d7);
                // depth-3 tree, left-biased <= preserves first-argmin tie semantics
                bool p;
                p = (a0 <= a1); float v01 = p ? d0 : d1; float b01 = p ? a0 : a1;
                p = (a2 <= a3); float v23 = p ? d2 : d3; float b23 = p ? a2 : a3;
                p = (a4 <= a5); float v45 = p ? d4 : d5; float b45 = p ? a4 : a5;
                p = (a6 <= a7); float v67 = p ? d6 : d7; float b67 = p ? a6 : a7;
                p = (b01 <= b23); float v03 = p ? v01 : v23; float b03 = p ? b01 : b23;
                p = (b45 <= b67); float v47 = p ? v45 : v67; float b47 = p ? b45 : b67;
                p = (b03 <= b47); float best = p ? v03 : v47;
                res[j] = x + best;
            }
            if (full4) {
                dst4[(i+8)*W4 + c4] = make_float4(res[0], res[1], res[2], res[3]);
            } else {
                // c4 == 517: only buffer cols 2068, 2069 are inside the domain
                dstp[(i+8)*WB + 4*c4 + 0] = res[0];
                dstp[(i+8)*WB + 4*c4 + 1] = res[1];
            }
        }

        // slide vertical windows to row i+1; reuse aT as next center row
        sT = f4sub(f4add(sT, aT), bT);
        sB = f4sub(f4add(sB, aB), xc);
        xc = aT;
    }
}

// ---------------- crop: bufA planar -> d_out HWC ----------------
__global__ void crop_kernel(float* __restrict__ out) {
    int x = blockIdx.x*blockDim.x + threadIdx.x;
    int y = blockIdx.y;
    if (x >= IMG) return;
    int br = y + RAD + GUARD;
    int bc = x + RAD + GUARD;
    float* o = out + (size_t)(y*IMG + x)*3;
    o[0] = g_bufA[0*PLANE + br*WB + bc];
    o[1] = g_bufA[1*PLANE + br*WB + bc];
    o[2] = g_bufA[2*PLANE + br*WB + bc];
}

extern "C" void kernel_launch(void* const* d_in, const int* in_sizes, int n_in,
                              void* d_out, int out_size) {
    (void)in_sizes; (void)n_in; (void)out_size;
    const float* img = (const float*)d_in[0];   // d_in[1], d_in[2] are fixed constant kernels
    float* out = (float*)d_out;

    dim3 pg((PLANE + 255)/256, 3);
    pad_kernel<<<pg, 256>>>(img);

    for (int it = 0; it < NITER; ++it)
        iter_kernel<<<dim3((NSTRIP + 3)/4, NRB, 3), 128>>>(it & 1);
    // it=0: A->B, it=1: B->A, ... it=9: B->A  => final state in g_bufA

    crop_kernel<<<dim3((IMG + 255)/256, IMG), 256>>>(out);
}

// round 3
// speedup vs baseline: 1.3304x; 1.0401x over previous
#include <cuda_runtime.h>

// ---------------- geometry ----------------
#define RAD    7
#define IMG    2048
#define DOM    2062            // IMG + 2*RAD : iterated domain
#define GUARD  8               // zero guard band around DOM (zero-pad semantics)
#define WB     2176            // buffer width in floats
#define W4     (WB/4)
#define HB     2080            // buffer height
#define PLANE  (HB*WB)
#define NSTRIP 19              // 19 strips * 28 float4 = 532 >= 516 domain float4 cols
#define SROWS  30              // 5 x 69 x 3 = 1035 blocks ~= one full wave (148 SM x 7)
#define NRB    69              // ceil(2062/30)
#define NITER  10

// ping-pong state, planar per channel, guard bands stay zero forever
__device__ float g_bufA[3*PLANE];
__device__ float g_bufB[3*PLANE];

// ---------------- pad: img (HWC, edge-pad 7) -> bufA planar; bufB = 0 ----------------
__global__ void pad_kernel(const float* __restrict__ img) {
    int idx = blockIdx.x*blockDim.x + threadIdx.x;
    if (idx >= PLANE) return;
    int ch = blockIdx.y;
    int br = idx / WB, bc = idx % WB;
    float v = 0.f;
    if (br >= GUARD && br < GUARD+DOM && bc >= GUARD && bc < GUARD+DOM) {
        int u = br - (GUARD+RAD);
        int w = bc - (GUARD+RAD);
        u = min(max(u,0), IMG-1);
        w = min(max(w,0), IMG-1);
        v = img[(u*IMG + w)*3 + ch];
    }
    g_bufA[ch*PLANE + idx] = v;
    g_bufB[ch*PLANE + idx] = 0.f;
}

__device__ __forceinline__ float4 f4add(float4 a, float4 b){
    return make_float4(a.x+b.x, a.y+b.y, a.z+b.z, a.w+b.w);
}
__device__ __forceinline__ float4 f4sub(float4 a, float4 b){
    return make_float4(a.x-b.x, a.y-b.y, a.z-b.z, a.w-b.w);
}

// rotate-left-1 key: (abs_bits << 1) | sign  — unsigned order == |value| order,
// bijective with the float bits (recover via rotate-right-1)
__device__ __forceinline__ unsigned keyof(float d) {
    unsigned b = __float_as_uint(d);
    return __funnelshift_l(b, b, 1);
}

// incremental left/right 8-windows from (fine[t-2], ownfine, fine[t+2], chunk sums)
// l[j] = sum w[j+1..j+8], r[j] = sum w[j+8..j+15] with w[k] = value at col 4*(t-2)+k
__device__ __forceinline__ void hwin_cs(float4 fm, float4 own, float4 fp,
                                        float Cm2, float Cm1, float Cown, float Cp1,
                                        float* l, float* r) {
    l[0] = (Cm2 - fm.x) + Cm1 + own.x;
    l[1] = l[0] - fm.y + own.y;
    l[2] = l[1] - fm.z + own.z;
    l[3] = l[2] - fm.w + own.w;
    r[0] = Cown + Cp1;
    r[1] = r[0] - own.x + fp.x;
    r[2] = r[1] - own.y + fp.y;
    r[3] = r[2] - own.z + fp.z;
}

// ---------------- one full side-window iteration, warp-autonomous ----------------
__global__ __launch_bounds__(128,7) void iter_kernel(int sel) {
    __shared__ float4 sF[3][4][32];   // [array: T,B,X][warp][lane] fine float4
    __shared__ float  sC[3][4][32];   // chunk sums

    const int t = threadIdx.x & 31;
    const int w = threadIdx.x >> 5;
    const int strip = blockIdx.x*4 + w;
    if (strip >= NSTRIP) return;      // safe: no __syncthreads in this kernel
    const int ch = blockIdx.z;
    const float* __restrict__ srcp = (sel ? g_bufB : g_bufA) + ch*PLANE;
    float*       __restrict__ dstp = (sel ? g_bufA : g_bufB) + ch*PLANE;
    const float4* __restrict__ src4 = reinterpret_cast<const float4*>(srcp);
    float4*       __restrict__ dst4 = reinterpret_cast<float4*>(dstp);

    const int c4 = strip*28 + t;      // buffer float4 column (max 535 < 544)
    const int r0 = blockIdx.y*SROWS;
    const int rend = min(r0 + SROWS, DOM);

    // warm-up: sT = buffer rows r0+1..r0+8, sB = rows r0+8..r0+15, xc = row r0+8
    float4 sT = make_float4(0,0,0,0), sB = make_float4(0,0,0,0), xc = make_float4(0,0,0,0);
    #pragma unroll
    for (int k = 1; k <= 15; ++k) {
        float4 v = __ldg(&src4[(r0+k)*W4 + c4]);
        if (k <= 8) sT = f4add(sT, v);
        if (k >= 8) sB = f4add(sB, v);
        if (k == 8) xc = v;
    }

    const bool isOut = (t >= 2) && (t < 30) && (c4 <= 517);
    const bool full4 = (c4 <= 516);
    const float S8  = 1.0f/64.0f;
    const float S15 = 1.0f/120.0f;

    for (int i = r0; i < rend; ++i) {
        // prefetch this row's slide inputs early (consumed only at loop bottom)
        float4 aT = __ldg(&src4[(i+9)*W4  + c4]);   // also next row's center
        float4 bT = __ldg(&src4[(i+1)*W4  + c4]);
        float4 aB = __ldg(&src4[(i+16)*W4 + c4]);

        float cT = (sT.x+sT.y)+(sT.z+sT.w);
        float cB = (sB.x+sB.y)+(sB.z+sB.w);
        float cX = (xc.x+xc.y)+(xc.z+xc.w);

        __syncwarp();
        sF[0][w][t] = sT; sC[0][w][t] = cT;
        sF[1][w][t] = sB; sC[1][w][t] = cB;
        sF[2][w][t] = xc; sC[2][w][t] = cX;
        __syncwarp();

        if (isOut) {
            float lA[4], rA[4], lB[4], rB[4], lX[4], rX[4];
            {
                float4 fm = sF[0][w][t-2], fp = sF[0][w][t+2];
                hwin_cs(fm, sT, fp, sC[0][w][t-2], sC[0][w][t-1], cT, sC[0][w][t+1], lA, rA);
            }
            {
                float4 fm = sF[1][w][t-2], fp = sF[1][w][t+2];
                hwin_cs(fm, sB, fp, sC[1][w][t-2], sC[1][w][t-1], cB, sC[1][w][t+1], lB, rB);
            }
            {
                float4 fm = sF[2][w][t-2], fp = sF[2][w][t+2];
                hwin_cs(fm, xc, fp, sC[2][w][t-2], sC[2][w][t-1], cX, sC[2][w][t+1], lX, rX);
            }

            const float cAj[4] = { sT.x, sT.y, sT.z, sT.w };
            const float cBj[4] = { sB.x, sB.y, sB.z, sB.w };
            const float xv [4] = { xc.x, xc.y, xc.z, xc.w };
            float res[4];
            #pragma unroll
            for (int j = 0; j < 4; ++j) {
                float fA = lA[j] + rA[j] - cAj[j];      // full-15 horiz of top sums
                float fB = lB[j] + rB[j] - cBj[j];      // full-15 horiz of bottom sums
                float lC = lA[j] + lB[j] - lX[j];       // left-8 of full-15 vertical
                float rC = rA[j] + rB[j] - rX[j];       // right-8 of full-15 vertical
                float x  = xv[j];
                // channel order matches reference stack: NW NE SW SE N S W E
                float d0 = fmaf(lA[j], S8,  -x);
                float d1 = fmaf(rA[j], S8,  -x);
                float d2 = fmaf(lB[j], S8,  -x);
                float d3 = fmaf(rB[j], S8,  -x);
                float d4 = fmaf(fA,    S15, -x);
                float d5 = fmaf(fB,    S15, -x);
                float d6 = fmaf(lC,    S15, -x);
                float d7 = fmaf(rC,    S15, -x);
                // min-|d| via rotated-bits unsigned keys, depth-3 IMNMX tree
                unsigned k0 = keyof(d0), k1 = keyof(d1), k2 = keyof(d2), k3 = keyof(d3);
                unsigned k4 = keyof(d4), k5 = keyof(d5), k6 = keyof(d6), k7 = keyof(d7);
                unsigned m = min(min(min(k0,k1), min(k2,k3)),
                                 min(min(k4,k5), min(k6,k7)));
                float best = __uint_as_float(__funnelshift_r(m, m, 1));
                res[j] = x + best;
            }
            if (full4) {
                dst4[(i+8)*W4 + c4] = make_float4(res[0], res[1], res[2], res[3]);
            } else {
                // c4 == 517: only buffer cols 2068, 2069 are inside the domain
                dstp[(i+8)*WB + 4*c4 + 0] = res[0];
                dstp[(i+8)*WB + 4*c4 + 1] = res[1];
            }
        }

        // slide vertical windows to row i+1; reuse aT as next center row
        sT = f4sub(f4add(sT, aT), bT);
        sB = f4sub(f4add(sB, aB), xc);
        xc = aT;
    }
}

// ---------------- crop: bufA planar -> d_out HWC ----------------
__global__ void crop_kernel(float* __restrict__ out) {
    int x = blockIdx.x*blockDim.x + threadIdx.x;
    int y = blockIdx.y;
    if (x >= IMG) return;
    int br = y + RAD + GUARD;
    int bc = x + RAD + GUARD;
    float* o = out + (size_t)(y*IMG + x)*3;
    o[0] = g_bufA[0*PLANE + br*WB + bc];
    o[1] = g_bufA[1*PLANE + br*WB + bc];
    o[2] = g_bufA[2*PLANE + br*WB + bc];
}

extern "C" void kernel_launch(void* const* d_in, const int* in_sizes, int n_in,
                              void* d_out, int out_size) {
    (void)in_sizes; (void)n_in; (void)out_size;
    const float* img = (const float*)d_in[0];   // d_in[1], d_in[2] are fixed constant kernels
    float* out = (float*)d_out;

    dim3 pg((PLANE + 255)/256, 3);
    pad_kernel<<<pg, 256>>>(img);

    for (int it = 0; it < NITER; ++it)
        iter_kernel<<<dim3(5, NRB, 3), 128>>>(it & 1);
    // it=0: A->B, it=1: B->A, ... it=9: B->A  => final state in g_bufA

    crop_kernel<<<dim3((IMG + 255)/256, IMG), 256>>>(out);
}